// round 13
// baseline (speedup 1.0000x reference)
#include <cuda_runtime.h>
#include <cstdint>

// ---------------------------------------------------------------------------
// Fully fused GRU acoustic model (single kernel):
//   encoder GRU(13->300) T=2048, fc+relu, decoder GRU(300->13) T=2048.
//
// 16 clusters x 8 CTAs x 512 thr. Cluster = 4 batches, processed as TWO
// pipelined groups of 2 batches. Per step:
//   waitA(t-1); stage1(A); sync; [tail(A)+arriveA || x prefetch];
//   waitB(t-1); stage1(B); sync; tail(B)+arriveB
// Each group's cluster mbarrier (count 8, parity t&1) is waited a full
// half-step after its arrives -> DSMEM + barrier latency hidden behind the
// other group's compute. Whh register-stationary (2 rows x 40k f32x2/thread).
// ---------------------------------------------------------------------------

#define KB   64
#define KT   2048
#define KF   13
#define KH   300
#define KCL  8      // CTAs per cluster
#define KBPC 4      // batches per cluster
#define KBPG 2      // batches per group
#define NG   2      // groups per cluster
#define KU   38     // hidden units per CTA (rank 7 uses 34)
#define KROWS 114   // 3 * KU gate rows per CTA
#define KTHR 512
#define KHP  320    // padded k extent (8 chunks * 40)
#define NCH  8      // k-chunks
#define CK   40     // k per chunk
#define CPAIR 20    // k-pairs per chunk
#define PSTR 18     // part row stride in floats

typedef unsigned long long u64t;

struct EncSmem {
    float h[NG][2][KBPG][KHP];   // hidden, [group][buf][m][k]
    float part[NG][KROWS][PSTR]; // partials [g][row][c*2+m]; reused as
                                 // emb/dgi scratch post-encoder
    float WihT[16][128];         // input weights transposed [f][row]
    float bsum[128];             // bih+bhh for r,z rows
    float bihN[64];              // bih for n rows (jl)
    float bhhN[64];              // bhh for n rows (jl)
    float xs[NG][2][KBPG][16];   // x_t ring per group (parity by step)
    unsigned long long barA, barB;  // cluster mbarriers, 8 arrivals/phase
};

__device__ __forceinline__ float sigm_fast(float v) {
    return __fdividef(1.0f, 1.0f + __expf(-v));
}
__device__ __forceinline__ float tanh_fast(float v) {
    return __fdividef(2.0f, 1.0f + __expf(-2.0f * v)) - 1.0f;
}
__device__ __forceinline__ void cluster_sync() {
    asm volatile("barrier.cluster.arrive.aligned;\n\t"
                 "barrier.cluster.wait.aligned;" ::: "memory");
}
__device__ __forceinline__ uint32_t smem_u32(const void* p) {
    uint32_t a;
    asm("{ .reg .u64 t; cvta.to.shared.u64 t, %1; cvt.u32.u64 %0, t; }"
        : "=r"(a) : "l"(p));
    return a;
}
__device__ __forceinline__ uint32_t mapa_u32(uint32_t laddr, uint32_t rank) {
    uint32_t ra;
    asm("mapa.shared::cluster.u32 %0, %1, %2;" : "=r"(ra) : "r"(laddr), "r"(rank));
    return ra;
}
__device__ __forceinline__ void st_cluster_f32(uint32_t addr, float v) {
    asm volatile("st.shared::cluster.f32 [%0], %1;" :: "r"(addr), "f"(v) : "memory");
}
__device__ __forceinline__ u64t lds_b64(uint32_t addr) {
    u64t v;
    asm volatile("ld.shared.b64 %0, [%1];" : "=l"(v) : "r"(addr));
    return v;
}
__device__ __forceinline__ u64t pack2(float lo, float hi) {
    u64t v;
    asm("mov.b64 %0, {%1, %2};" : "=l"(v) : "f"(lo), "f"(hi));
    return v;
}
__device__ __forceinline__ float hadd2(u64t v) {
    float lo, hi;
    asm("mov.b64 {%0, %1}, %2;" : "=f"(lo), "=f"(hi) : "l"(v));
    return lo + hi;
}
__device__ __forceinline__ void fma2(u64t& d, u64t a, u64t b) {
    asm("fma.rn.f32x2 %0, %1, %2, %0;" : "+l"(d) : "l"(a), "l"(b));
}
__device__ __forceinline__ void mbar_init(uint32_t addr, uint32_t count) {
    asm volatile("mbarrier.init.shared.b64 [%0], %1;" :: "r"(addr), "r"(count)
                 : "memory");
}
__device__ __forceinline__ void mbar_arrive_cluster(uint32_t remote_addr) {
    asm volatile("mbarrier.arrive.shared::cluster.b64 _, [%0];"
                 :: "r"(remote_addr) : "memory");
}
__device__ __forceinline__ void mbar_wait_acq(uint32_t bar, uint32_t parity) {
    uint32_t done;
    asm volatile(
        "{\n\t.reg .pred p;\n\t"
        "mbarrier.try_wait.parity.acquire.cluster.shared::cta.b64 p, [%1], %2, 0x989680;\n\t"
        "selp.b32 %0, 1, 0, p;\n\t}"
        : "=r"(done) : "r"(bar), "r"(parity) : "memory");
    if (!done) {
        asm volatile(
            "{\n\t.reg .pred P1;\n\t"
            "WL_%=:\n\t"
            "mbarrier.try_wait.parity.acquire.cluster.shared::cta.b64 P1, [%0], %1, 0x989680;\n\t"
            "@P1 bra.uni WD_%=;\n\t"
            "bra.uni WL_%=;\n\t"
            "WD_%=:\n\t}"
            :: "r"(bar), "r"(parity) : "memory");
    }
}

__global__ void __cluster_dims__(KCL, 1, 1) __launch_bounds__(KTHR, 1)
enc_kernel(const float* __restrict__ x,    const float* __restrict__ Wih,
           const float* __restrict__ Whh,  const float* __restrict__ bih,
           const float* __restrict__ bhh,
           const float* __restrict__ fcW,  const float* __restrict__ fcb,
           const float* __restrict__ dWih, const float* __restrict__ dWhh,
           const float* __restrict__ dbih, const float* __restrict__ dbhh,
           float* __restrict__ out, int writeEmb)
{
    __shared__ __align__(16) EncSmem S;
    const int tid     = threadIdx.x;
    const int cluster = blockIdx.x / KCL;
    const int rank    = blockIdx.x % KCL;
    const int u0      = rank * KU;
    const int ucnt    = (KH - u0 < KU) ? (KH - u0) : KU;

    const int rp = tid & 63;       // row-pair index, active < 57
    const int c  = tid >> 6;       // k-chunk 0..7 (uniform per warp)
    const int r0 = 2 * rp;         // gate rows r0, r0+1
    const int k0 = c * CK;

    // ---- init smem ----
    for (int i = tid; i < NG * 2 * KBPG * KHP; i += KTHR) (&S.h[0][0][0][0])[i] = 0.f;
    for (int i = tid; i < 16 * 128; i += KTHR) (&S.WihT[0][0])[i] = 0.f;
    for (int i = tid; i < 128; i += KTHR) S.bsum[i] = 0.f;
    for (int i = tid; i < 64; i += KTHR) { S.bihN[i] = 0.f; S.bhhN[i] = 0.f; }
    if (tid == 0) {
        mbar_init(smem_u32(&S.barA), KCL);
        mbar_init(smem_u32(&S.barB), KCL);
    }
    __syncthreads();

    for (int i = tid; i < 3 * ucnt * KF; i += KTHR) {
        const int f  = i % KF;
        const int rr = i / KF;
        const int g = rr / ucnt, jl = rr % ucnt;
        S.WihT[f][g * KU + jl] = Wih[(size_t)(g * KH + u0 + jl) * KF + f];
    }
    if (tid < KROWS) {
        const int g = tid / KU, jl = tid % KU;
        if (jl < ucnt) {
            const float bi = bih[g * KH + u0 + jl];
            const float bh = bhh[g * KH + u0 + jl];
            if (g < 2) S.bsum[tid] = bi + bh;
            else       { S.bihN[jl] = bi; S.bhhN[jl] = bh; }
        }
    }
    // x_0 for both groups
    if (tid < KBPC * KF) {
        const int gg = tid / (KBPG * KF);
        const int r2 = tid % (KBPG * KF);
        const int m = r2 / KF, f = r2 % KF;
        S.xs[gg][0][m][f] =
            x[((size_t)(cluster * KBPC + gg * KBPG + m) * KT + 0) * KF + f];
    }

    // ---- load this thread's TWO gate-rows of packed Whh k-pairs ----
    u64t Wa[CPAIR], Wb[CPAIR];
    {
        const int ga = r0 / KU,       jla = r0 % KU;
        const int gb = (r0 + 1) / KU, jlb = (r0 + 1) % KU;
        const bool actA = (rp < 57) && (r0 < KROWS)     && (jla < ucnt);
        const bool actB = (rp < 57) && (r0 + 1 < KROWS) && (jlb < ucnt);
        const float* wrA = actA ? (Whh + (size_t)(ga * KH + u0 + jla) * KH) : Whh;
        const float* wrB = actB ? (Whh + (size_t)(gb * KH + u0 + jlb) * KH) : Whh;
        #pragma unroll
        for (int i = 0; i < CPAIR; ++i) {
            const int k = k0 + 2 * i;
            float a0 = 0.f, a1 = 0.f, b0 = 0.f, b1 = 0.f;
            if (actA && k < KH)     a0 = wrA[k];
            if (actA && k + 1 < KH) a1 = wrA[k + 1];
            if (actB && k < KH)     b0 = wrB[k];
            if (actB && k + 1 < KH) b1 = wrB[k + 1];
            Wa[i] = pack2(a0, a1);
            Wb[i] = pack2(b0, b1);
        }
    }

    const uint32_t hbaseL = smem_u32(&S.h[0][0][0][0]);
    const uint32_t barAL  = smem_u32(&S.barA);
    const uint32_t barBL  = smem_u32(&S.barB);
    uint32_t R0 = mapa_u32(hbaseL, 0), R1 = mapa_u32(hbaseL, 1),
             R2 = mapa_u32(hbaseL, 2), R3 = mapa_u32(hbaseL, 3),
             R4 = mapa_u32(hbaseL, 4), R5 = mapa_u32(hbaseL, 5),
             R6 = mapa_u32(hbaseL, 6), R7 = mapa_u32(hbaseL, 7);

    __syncthreads();
    cluster_sync();   // peers' h buffers + mbarriers initialized

    int p = 0;

    // ---- stage 1 for group g: partial gh into part[g] ----
    auto stage1 = [&](int g, int pp) {
        if (rp < 57) {
            const uint32_t hb =
                hbaseL + (uint32_t)(((g * 2 + pp) * KBPG) * KHP + k0) * 4;
            u64t A0 = 0, A1 = 0, B0 = 0, B1 = 0;
            #pragma unroll
            for (int i = 0; i < CPAIR; ++i) {
                const u64t h0 = lds_b64(hb + i * 8);
                const u64t h1 = lds_b64(hb + KHP * 4 + i * 8);
                const u64t wa = Wa[i], wb = Wb[i];
                fma2(A0, wa, h0); fma2(A1, wa, h1);
                fma2(B0, wb, h0); fma2(B1, wb, h1);
            }
            *reinterpret_cast<float2*>(&S.part[g][r0][c * 2]) =
                make_float2(hadd2(A0), hadd2(A1));
            *reinterpret_cast<float2*>(&S.part[g][r0 + 1][c * 2]) =
                make_float2(hadd2(B0), hadd2(B1));
        }
    };

    // ---- tail for group g: reduce + gi + gates + remote h broadcast ----
    auto tail = [&](int g, int t, int pp) {
        if (tid < KBPG * KU) {
            const int jl = tid >> 1, m = tid & 1;
            if (jl < ucnt) {
                const float* pR = S.part[g][jl];
                const float* pZ = S.part[g][KU + jl];
                const float* pN = S.part[g][2 * KU + jl];
                float pr = 0.f, pz = 0.f, pn = 0.f;
                #pragma unroll
                for (int cc = 0; cc < NCH; ++cc) {
                    pr += pR[cc * 2 + m];
                    pz += pZ[cc * 2 + m];
                    pn += pN[cc * 2 + m];
                }
                const float* xr = S.xs[g][t & 1][m];
                float gr = 0.f, gz = 0.f, gn = 0.f;
                #pragma unroll
                for (int f = 0; f < KF; ++f) {
                    const float xf = xr[f];
                    gr = fmaf(S.WihT[f][jl], xf, gr);
                    gz = fmaf(S.WihT[f][KU + jl], xf, gz);
                    gn = fmaf(S.WihT[f][2 * KU + jl], xf, gn);
                }
                const float r = sigm_fast(pr + gr + S.bsum[jl]);
                const float z = sigm_fast(pz + gz + S.bsum[KU + jl]);
                const float n = tanh_fast(gn + S.bihN[jl] + r * (pn + S.bhhN[jl]));
                const float hn = (1.0f - z) * n + z * S.h[g][pp][m][u0 + jl];
                const uint32_t off =
                    (uint32_t)(((g * 2 + (pp ^ 1)) * KBPG + m) * KHP + u0 + jl) * 4;
                st_cluster_f32(R0 + off, hn); st_cluster_f32(R1 + off, hn);
                st_cluster_f32(R2 + off, hn); st_cluster_f32(R3 + off, hn);
                st_cluster_f32(R4 + off, hn); st_cluster_f32(R5 + off, hn);
                st_cluster_f32(R6 + off, hn); st_cluster_f32(R7 + off, hn);
            }
        }
    };

    auto arrive_all = [&](uint32_t barLoc) {
        asm volatile("fence.acq_rel.cluster;" ::: "memory");
        #pragma unroll
        for (int rr = 0; rr < KCL; ++rr)
            mbar_arrive_cluster(mapa_u32(barLoc, (uint32_t)rr));
    };

    for (int t = 0; t < KT; ++t) {
        // ================= group A half-step =================
        if (t > 0) mbar_wait_acq(barAL, (uint32_t)((t - 1) & 1));
        stage1(0, p);
        __syncthreads();
        if (tid < 96) {
            tail(0, t, p);
            asm volatile("bar.sync 1, 96;" ::: "memory");
            if (tid == 0) arrive_all(barAL);
        } else if (tid < 96 + KBPC * KF) {
            // prefetch x_{t+1} for both groups (overlaps tail A)
            if (t + 1 < KT) {
                const int idx = tid - 96;
                const int gg = idx / (KBPG * KF);
                const int r2 = idx % (KBPG * KF);
                const int pm = r2 / KF, pf = r2 % KF;
                S.xs[gg][(t + 1) & 1][pm][pf] =
                    x[((size_t)(cluster * KBPC + gg * KBPG + pm) * KT + (t + 1)) * KF + pf];
            }
        }
        // ================= group B half-step =================
        if (t > 0) mbar_wait_acq(barBL, (uint32_t)((t - 1) & 1));
        stage1(1, p);
        __syncthreads();
        if (tid < 96) {
            tail(1, t, p);
            asm volatile("bar.sync 1, 96;" ::: "memory");
            if (tid == 0) arrive_all(barBL);
        }
        p ^= 1;
    }
    mbar_wait_acq(barAL, (uint32_t)((KT - 1) & 1));
    mbar_wait_acq(barBL, (uint32_t)((KT - 1) & 1));
    __syncthreads();

    // =======================================================================
    // Fused fc + relu + decoder: ranks 0-3 handle batch (g = rank>>1,
    // m = rank&1). Full final h for every batch is in local S.h[g][p].
    // =======================================================================
    if (rank < KBPC) {
        const int g = rank >> 1, m = rank & 1;
        const int b = cluster * KBPC + g * KBPG + m;
        float* embS = &S.part[0][0][0];     // 300 floats (reuse scratch)
        float* dgiS = embS + 304;           // 39 floats

        const float* hrow = &S.h[g][p][m][0];
        for (int j = tid; j < KH; j += KTHR) {
            const float4* wr = reinterpret_cast<const float4*>(fcW + (size_t)j * KH);
            float s0 = 0.f, s1 = 0.f, s2 = 0.f, s3 = 0.f;
            #pragma unroll 5
            for (int k = 0; k < KH / 4; ++k) {
                const float4 w4 = wr[k];
                const float4 h4 = *reinterpret_cast<const float4*>(&hrow[k * 4]);
                s0 = fmaf(w4.x, h4.x, s0); s1 = fmaf(w4.y, h4.y, s1);
                s2 = fmaf(w4.z, h4.z, s2); s3 = fmaf(w4.w, h4.w, s3);
            }
            float s = fcb[j] + ((s0 + s1) + (s2 + s3));
            s = fmaxf(s, 0.0f);
            embS[j] = s;
            if (writeEmb)
                out[(size_t)KB * KT * KF + (size_t)b * KH + j] = s;
        }
        __syncthreads();

        if (tid < 3 * KF) {
            const float4* wr = reinterpret_cast<const float4*>(dWih + (size_t)tid * KH);
            float s0 = 0.f, s1 = 0.f, s2 = 0.f, s3 = 0.f;
            #pragma unroll 5
            for (int k = 0; k < KH / 4; ++k) {
                const float4 w4 = wr[k];
                const float4 h4 = *reinterpret_cast<const float4*>(&embS[k * 4]);
                s0 = fmaf(w4.x, h4.x, s0); s1 = fmaf(w4.y, h4.y, s1);
                s2 = fmaf(w4.z, h4.z, s2); s3 = fmaf(w4.w, h4.w, s3);
            }
            dgiS[tid] = dbih[tid] + ((s0 + s1) + (s2 + s3));
        }
        __syncthreads();

        if (tid < 32) {
            const int lane = tid;
            const bool act = (lane < KF);
            float wr_[KF], wz_[KF], wn_[KF];
            #pragma unroll
            for (int k = 0; k < KF; ++k) {
                wr_[k] = act ? dWhh[(size_t)lane * KF + k]            : 0.f;
                wz_[k] = act ? dWhh[(size_t)(KF + lane) * KF + k]     : 0.f;
                wn_[k] = act ? dWhh[(size_t)(2 * KF + lane) * KF + k] : 0.f;
            }
            const float bhr = act ? dbhh[lane]          : 0.f;
            const float bhz = act ? dbhh[KF + lane]     : 0.f;
            const float bhn = act ? dbhh[2 * KF + lane] : 0.f;
            const float dgr = act ? dgiS[lane]          : 0.f;
            const float dgz = act ? dgiS[KF + lane]     : 0.f;
            const float dgn = act ? dgiS[2 * KF + lane] : 0.f;
            float hv = 0.f;
            float* op = out + (size_t)b * KT * KF;

            for (int t = 0; t < KT; ++t) {
                float sr = bhr, sz = bhz, sn = bhn;
                #pragma unroll
                for (int k = 0; k < KF; ++k) {
                    const float hk = __shfl_sync(0xffffffffu, hv, k);
                    sr = fmaf(wr_[k], hk, sr);
                    sz = fmaf(wz_[k], hk, sz);
                    sn = fmaf(wn_[k], hk, sn);
                }
                if (act) {
                    const float r = sigm_fast(dgr + sr);
                    const float z = sigm_fast(dgz + sz);
                    const float n = tanh_fast(dgn + r * sn);
                    hv = (1.0f - z) * n + z * hv;
                    op[(size_t)t * KF + lane] = hv;
                }
            }
        }
    }
}

extern "C" void kernel_launch(void* const* d_in, const int* in_sizes, int n_in,
                              void* d_out, int out_size)
{
    const float* x    = (const float*)d_in[0];
    const float* eWih = (const float*)d_in[1];
    const float* eWhh = (const float*)d_in[2];
    const float* ebih = (const float*)d_in[3];
    const float* ebhh = (const float*)d_in[4];
    const float* fcW  = (const float*)d_in[5];
    const float* fcb  = (const float*)d_in[6];
    const float* dWih = (const float*)d_in[7];
    const float* dWhh = (const float*)d_in[8];
    const float* dbih = (const float*)d_in[9];
    const float* dbhh = (const float*)d_in[10];
    float* out = (float*)d_out;

    const int writeEmb = (out_size >= KB * KT * KF + KB * KH) ? 1 : 0;

    enc_kernel<<<(KB / KBPC) * KCL, KTHR>>>(
        x, eWih, eWhh, ebih, ebhh, fcW, fcb, dWih, dWhh, dbih, dbhh,
        out, writeEmb);
}

// round 14
// speedup vs baseline: 1.0998x; 1.0998x over previous
#include <cuda_runtime.h>
#include <cstdint>

// ---------------------------------------------------------------------------
// Fully fused GRU acoustic model (single kernel):
//   encoder GRU(13->300) T=2048, fc+relu, decoder GRU(300->13) T=2048.
//
// 16 clusters x 8 CTAs x 512 thr. Cluster = 4 batches. Encoder: each thread
// owns TWO gate-rows x one 40-k chunk of Whh packed f32x2 in registers; h
// loaded via ld.shared.v2.u64 (16B broadcast). Per step: stage1 (all warps),
// syncthreads, tail (warps 0-4: reduce + gates + DSMEM push to 8 peers)
// overlapped with gi(t+1) on warps 5-9 and x(t+2) prefetch on warps 10-11,
// then ONE cluster barrier. (R8 sync structure + R12 compute pieces.)
// ---------------------------------------------------------------------------

#define KB   64
#define KT   2048
#define KF   13
#define KH   300
#define KCL  8      // CTAs per cluster
#define KBPC 4      // batches per cluster
#define KU   38     // hidden units per CTA (rank 7 uses 34)
#define KROWS 114   // 3 * KU gate rows per CTA
#define KTHR 512
#define KHP  320    // padded k extent per batch row (8 chunks * 40)
#define NCH  8      // k-chunks
#define CK   40     // k per chunk
#define CPAIR 20    // k-pairs per chunk
#define PSTR 36     // part row stride in floats

typedef unsigned long long u64t;

struct EncSmem {
    float h[2][KBPC][KHP];       // double-buffered hidden, [buf][batch][k]
    float part[KROWS][PSTR];     // partials [row][chunk*4+batch]; reused as
                                 // emb/dgi scratch post-encoder
    float WihT[16][128];         // input weights transposed [f][row]
    float gis[2][120][KBPC];     // double-buffered gi+bih, [buf][row][batch]
    float bhhS[128];             // bhh per gate-row
    float xs[2][KBPC][16];       // x_t ring (parity by step)
};

__device__ __forceinline__ float sigm_fast(float v) {
    return __fdividef(1.0f, 1.0f + __expf(-v));
}
__device__ __forceinline__ float tanh_fast(float v) {
    return __fdividef(2.0f, 1.0f + __expf(-2.0f * v)) - 1.0f;
}
__device__ __forceinline__ void cluster_sync() {
    asm volatile("barrier.cluster.arrive.aligned;\n\t"
                 "barrier.cluster.wait.aligned;" ::: "memory");
}
__device__ __forceinline__ uint32_t smem_u32(const void* p) {
    uint32_t a;
    asm("{ .reg .u64 t; cvta.to.shared.u64 t, %1; cvt.u32.u64 %0, t; }"
        : "=r"(a) : "l"(p));
    return a;
}
__device__ __forceinline__ uint32_t mapa_u32(uint32_t laddr, uint32_t rank) {
    uint32_t ra;
    asm("mapa.shared::cluster.u32 %0, %1, %2;" : "=r"(ra) : "r"(laddr), "r"(rank));
    return ra;
}
__device__ __forceinline__ void st_cluster_f32(uint32_t addr, float v) {
    asm volatile("st.shared::cluster.f32 [%0], %1;" :: "r"(addr), "f"(v) : "memory");
}
__device__ __forceinline__ void lds_v2u64(uint32_t addr, u64t& a, u64t& b) {
    asm volatile("ld.shared.v2.u64 {%0, %1}, [%2];" : "=l"(a), "=l"(b) : "r"(addr));
}
__device__ __forceinline__ u64t pack2(float lo, float hi) {
    u64t v;
    asm("mov.b64 %0, {%1, %2};" : "=l"(v) : "f"(lo), "f"(hi));
    return v;
}
__device__ __forceinline__ float hadd2(u64t v) {
    float lo, hi;
    asm("mov.b64 {%0, %1}, %2;" : "=f"(lo), "=f"(hi) : "l"(v));
    return lo + hi;
}
__device__ __forceinline__ void fma2(u64t& d, u64t a, u64t b) {
    asm("fma.rn.f32x2 %0, %1, %2, %0;" : "+l"(d) : "l"(a), "l"(b));
}

__global__ void __cluster_dims__(KCL, 1, 1) __launch_bounds__(KTHR, 1)
enc_kernel(const float* __restrict__ x,    const float* __restrict__ Wih,
           const float* __restrict__ Whh,  const float* __restrict__ bih,
           const float* __restrict__ bhh,
           const float* __restrict__ fcW,  const float* __restrict__ fcb,
           const float* __restrict__ dWih, const float* __restrict__ dWhh,
           const float* __restrict__ dbih, const float* __restrict__ dbhh,
           float* __restrict__ out, int writeEmb)
{
    __shared__ __align__(16) EncSmem S;
    const int tid     = threadIdx.x;
    const int cluster = blockIdx.x / KCL;
    const int rank    = blockIdx.x % KCL;
    const int u0      = rank * KU;
    const int ucnt    = (KH - u0 < KU) ? (KH - u0) : KU;

    const int rp = tid & 63;       // row-pair index, active < 57
    const int c  = tid >> 6;       // k-chunk 0..7 (uniform per warp)
    const int r0 = 2 * rp;         // gate rows r0, r0+1
    const int k0 = c * CK;         // 16B-aligned k offset

    // ---- init smem ----
    for (int i = tid; i < 2 * KBPC * KHP; i += KTHR) (&S.h[0][0][0])[i] = 0.f;
    for (int i = tid; i < 16 * 128; i += KTHR) (&S.WihT[0][0])[i] = 0.f;
    for (int i = tid; i < 128; i += KTHR) S.bhhS[i] = 0.f;
    __syncthreads();

    for (int i = tid; i < 3 * ucnt * KF; i += KTHR) {
        const int f  = i % KF;
        const int rr = i / KF;
        const int g = rr / ucnt, jl = rr % ucnt;
        S.WihT[f][g * KU + jl] = Wih[(size_t)(g * KH + u0 + jl) * KF + f];
    }
    if (tid < KROWS) {
        const int g = tid / KU, jl = tid % KU;
        if (jl < ucnt) S.bhhS[tid] = bhh[g * KH + u0 + jl];
    }
    // xs[0] = x_0 (for gis[0] precompute), xs[1] = x_1 (for step-0 gi warps)
    if (tid < KBPC * KF) {
        const int m = tid / KF, f = tid % KF;
        S.xs[0][m][f] = x[((size_t)(cluster * KBPC + m) * KT + 0) * KF + f];
    } else if (tid >= 160 && tid < 160 + KBPC * KF) {
        const int idx = tid - 160;
        const int m = idx / KF, f = idx % KF;
        S.xs[1][m][f] = x[((size_t)(cluster * KBPC + m) * KT + 1) * KF + f];
    }

    // ---- load this thread's TWO gate-rows of packed Whh k-pairs ----
    u64t Wa[CPAIR], Wb[CPAIR];
    {
        const int ga = r0 / KU,       jla = r0 % KU;
        const int gb = (r0 + 1) / KU, jlb = (r0 + 1) % KU;
        const bool actA = (rp < 57) && (r0 < KROWS)     && (jla < ucnt);
        const bool actB = (rp < 57) && (r0 + 1 < KROWS) && (jlb < ucnt);
        const float* wrA = actA ? (Whh + (size_t)(ga * KH + u0 + jla) * KH) : Whh;
        const float* wrB = actB ? (Whh + (size_t)(gb * KH + u0 + jlb) * KH) : Whh;
        #pragma unroll
        for (int i = 0; i < CPAIR; ++i) {
            const int k = k0 + 2 * i;
            float a0 = 0.f, a1 = 0.f, b0 = 0.f, b1 = 0.f;
            if (actA && k < KH)     a0 = wrA[k];
            if (actA && k + 1 < KH) a1 = wrA[k + 1];
            if (actB && k < KH)     b0 = wrB[k];
            if (actB && k + 1 < KH) b1 = wrB[k + 1];
            Wa[i] = pack2(a0, a1);
            Wb[i] = pack2(b0, b1);
        }
    }
    __syncthreads();

    // ---- precompute gis[0] from xs[0] (includes bih) ----
    if (tid < KBPC * KU) {
        const int jl = tid >> 2, m = tid & 3;
        if (jl < ucnt) {
            const float* xr = S.xs[0][m];
            float gr = bih[u0 + jl], gz = bih[KH + u0 + jl], gn = bih[2 * KH + u0 + jl];
            #pragma unroll
            for (int f = 0; f < KF; ++f) {
                const float xf = xr[f];
                gr = fmaf(S.WihT[f][jl], xf, gr);
                gz = fmaf(S.WihT[f][KU + jl], xf, gz);
                gn = fmaf(S.WihT[f][2 * KU + jl], xf, gn);
            }
            S.gis[0][jl][m] = gr;
            S.gis[0][KU + jl][m] = gz;
            S.gis[0][2 * KU + jl][m] = gn;
        }
    }

    // ---- hoisted DSMEM peer base addresses + step offsets ----
    const uint32_t hbaseL = smem_u32(&S.h[0][0][0]);
    uint32_t R0 = mapa_u32(hbaseL, 0), R1 = mapa_u32(hbaseL, 1),
             R2 = mapa_u32(hbaseL, 2), R3 = mapa_u32(hbaseL, 3),
             R4 = mapa_u32(hbaseL, 4), R5 = mapa_u32(hbaseL, 5),
             R6 = mapa_u32(hbaseL, 6), R7 = mapa_u32(hbaseL, 7);
    const int jl_t = tid >> 2, m_t = tid & 3;                    // tail mapping
    const uint32_t offA = ((KBPC + m_t) * KHP + u0 + jl_t) * 4;  // write h[1]
    const uint32_t offB = ((m_t) * KHP + u0 + jl_t) * 4;         // write h[0]

    __syncthreads();
    cluster_sync();   // peers' h buffers initialized before any remote store

    int p = 0;

    for (int t = 0; t < KT; ++t) {
        // ---- stage 1: two rows x one chunk; 16B h loads; f32x2 FMA ----
        if (rp < 57) {
            const uint32_t hb = hbaseL + (uint32_t)(p * KBPC * KHP + k0) * 4;
            u64t A0 = 0, A1 = 0, A2 = 0, A3 = 0;   // row r0, batches 0..3
            u64t B0 = 0, B1 = 0, B2 = 0, B3 = 0;   // row r0+1
            #pragma unroll
            for (int i = 0; i < CPAIR / 2; ++i) {
                u64t h0a, h0b, h1a, h1b, h2a, h2b, h3a, h3b;
                lds_v2u64(hb + i * 16,                 h0a, h0b);
                lds_v2u64(hb + KHP * 4 + i * 16,       h1a, h1b);
                lds_v2u64(hb + 2 * KHP * 4 + i * 16,   h2a, h2b);
                lds_v2u64(hb + 3 * KHP * 4 + i * 16,   h3a, h3b);
                const u64t wa0 = Wa[2 * i], wa1 = Wa[2 * i + 1];
                const u64t wb0 = Wb[2 * i], wb1 = Wb[2 * i + 1];
                fma2(A0, wa0, h0a); fma2(A0, wa1, h0b);
                fma2(A1, wa0, h1a); fma2(A1, wa1, h1b);
                fma2(A2, wa0, h2a); fma2(A2, wa1, h2b);
                fma2(A3, wa0, h3a); fma2(A3, wa1, h3b);
                fma2(B0, wb0, h0a); fma2(B0, wb1, h0b);
                fma2(B1, wb0, h1a); fma2(B1, wb1, h1b);
                fma2(B2, wb0, h2a); fma2(B2, wb1, h2b);
                fma2(B3, wb0, h3a); fma2(B3, wb1, h3b);
            }
            *reinterpret_cast<float4*>(&S.part[r0][c * 4]) =
                make_float4(hadd2(A0), hadd2(A1), hadd2(A2), hadd2(A3));
            *reinterpret_cast<float4*>(&S.part[r0 + 1][c * 4]) =
                make_float4(hadd2(B0), hadd2(B1), hadd2(B2), hadd2(B3));
        }
        __syncthreads();

        if (tid < 160) {
            // ---- tail: reduce 8 chunks, gates, DSMEM broadcast ----
            if (tid < KBPC * KU && jl_t < ucnt) {
                const int jl = jl_t, m = m_t;
                const float* pR = S.part[jl];
                const float* pZ = S.part[KU + jl];
                const float* pN = S.part[2 * KU + jl];
                float pr = 0.f, pz = 0.f, pn = 0.f;
                #pragma unroll
                for (int cc = 0; cc < NCH; ++cc) {
                    pr += pR[cc * 4 + m];
                    pz += pZ[cc * 4 + m];
                    pn += pN[cc * 4 + m];
                }
                const float* gi = &S.gis[t & 1][0][0];
                const float r = sigm_fast(pr + gi[jl * 4 + m] + S.bhhS[jl]);
                const float z = sigm_fast(pz + gi[(KU + jl) * 4 + m] + S.bhhS[KU + jl]);
                const float n = tanh_fast(gi[(2 * KU + jl) * 4 + m]
                                          + r * (pn + S.bhhS[2 * KU + jl]));
                const float hn = (1.0f - z) * n + z * S.h[p][m][u0 + jl];
                const uint32_t off = p ? offB : offA;
                st_cluster_f32(R0 + off, hn); st_cluster_f32(R1 + off, hn);
                st_cluster_f32(R2 + off, hn); st_cluster_f32(R3 + off, hn);
                st_cluster_f32(R4 + off, hn); st_cluster_f32(R5 + off, hn);
                st_cluster_f32(R6 + off, hn); st_cluster_f32(R7 + off, hn);
            }
        } else if (tid < 160 + KBPC * KU) {
            // ---- gi for step t+1 (h-independent), on otherwise-idle warps ----
            if (t + 1 < KT) {
                const int idx = tid - 160;
                const int jl = idx >> 2, m = idx & 3;
                if (jl < ucnt) {
                    const float* xr = S.xs[(t + 1) & 1][m];
                    float gr = bih[u0 + jl], gz = bih[KH + u0 + jl],
                          gn = bih[2 * KH + u0 + jl];
                    #pragma unroll
                    for (int f = 0; f < KF; ++f) {
                        const float xf = xr[f];
                        gr = fmaf(S.WihT[f][jl], xf, gr);
                        gz = fmaf(S.WihT[f][KU + jl], xf, gz);
                        gn = fmaf(S.WihT[f][2 * KU + jl], xf, gn);
                    }
                    S.gis[(t + 1) & 1][jl][m] = gr;
                    S.gis[(t + 1) & 1][KU + jl][m] = gz;
                    S.gis[(t + 1) & 1][2 * KU + jl][m] = gn;
                }
            }
        } else if (tid < 312 + KBPC * KF) {
            // ---- prefetch x_{t+2} into the free xs buffer ----
            if (t + 2 < KT) {
                const int idx = tid - 312;
                const int pm = idx / KF, pf = idx % KF;
                S.xs[(t + 2) & 1][pm][pf] =
                    x[((size_t)(cluster * KBPC + pm) * KT + (t + 2)) * KF + pf];
            }
        }

        cluster_sync();   // single per-step barrier (release + acquire)
        p ^= 1;
    }
    __syncthreads();

    // =======================================================================
    // Fused fc + relu + decoder: ranks 0-3 handle batch m = rank.
    // =======================================================================
    if (rank < KBPC) {
        const int m = rank;
        const int b = cluster * KBPC + m;
        float* embS = &S.part[0][0];       // 300 floats (reuse part scratch)
        float* dgiS = embS + 304;          // 39 floats

        const float* hrow = &S.h[p][m][0];
        for (int j = tid; j < KH; j += KTHR) {
            const float4* wr = reinterpret_cast<const float4*>(fcW + (size_t)j * KH);
            float s0 = 0.f, s1 = 0.f, s2 = 0.f, s3 = 0.f;
            #pragma unroll 5
            for (int k = 0; k < KH / 4; ++k) {
                const float4 w4 = wr[k];
                const float4 h4 = *reinterpret_cast<const float4*>(&hrow[k * 4]);
                s0 = fmaf(w4.x, h4.x, s0); s1 = fmaf(w4.y, h4.y, s1);
                s2 = fmaf(w4.z, h4.z, s2); s3 = fmaf(w4.w, h4.w, s3);
            }
            float s = fcb[j] + ((s0 + s1) + (s2 + s3));
            s = fmaxf(s, 0.0f);
            embS[j] = s;
            if (writeEmb)
                out[(size_t)KB * KT * KF + (size_t)b * KH + j] = s;
        }
        __syncthreads();

        if (tid < 3 * KF) {
            const float4* wr = reinterpret_cast<const float4*>(dWih + (size_t)tid * KH);
            float s0 = 0.f, s1 = 0.f, s2 = 0.f, s3 = 0.f;
            #pragma unroll 5
            for (int k = 0; k < KH / 4; ++k) {
                const float4 w4 = wr[k];
                const float4 h4 = *reinterpret_cast<const float4*>(&embS[k * 4]);
                s0 = fmaf(w4.x, h4.x, s0); s1 = fmaf(w4.y, h4.y, s1);
                s2 = fmaf(w4.z, h4.z, s2); s3 = fmaf(w4.w, h4.w, s3);
            }
            dgiS[tid] = dbih[tid] + ((s0 + s1) + (s2 + s3));
        }
        __syncthreads();

        if (tid < 32) {
            const int lane = tid;
            const bool act = (lane < KF);
            float wr_[KF], wz_[KF], wn_[KF];
            #pragma unroll
            for (int k = 0; k < KF; ++k) {
                wr_[k] = act ? dWhh[(size_t)lane * KF + k]            : 0.f;
                wz_[k] = act ? dWhh[(size_t)(KF + lane) * KF + k]     : 0.f;
                wn_[k] = act ? dWhh[(size_t)(2 * KF + lane) * KF + k] : 0.f;
            }
            const float bhr = act ? dbhh[lane]          : 0.f;
            const float bhz = act ? dbhh[KF + lane]     : 0.f;
            const float bhn = act ? dbhh[2 * KF + lane] : 0.f;
            const float dgr = act ? dgiS[lane]          : 0.f;
            const float dgz = act ? dgiS[KF + lane]     : 0.f;
            const float dgn = act ? dgiS[2 * KF + lane] : 0.f;
            float hv = 0.f;
            float* op = out + (size_t)b * KT * KF;

            for (int t = 0; t < KT; ++t) {
                float sr = bhr, sz = bhz, sn = bhn;
                #pragma unroll
                for (int k = 0; k < KF; ++k) {
                    const float hk = __shfl_sync(0xffffffffu, hv, k);
                    sr = fmaf(wr_[k], hk, sr);
                    sz = fmaf(wz_[k], hk, sz);
                    sn = fmaf(wn_[k], hk, sn);
                }
                if (act) {
                    const float r = sigm_fast(dgr + sr);
                    const float z = sigm_fast(dgz + sz);
                    const float n = tanh_fast(dgn + r * sn);
                    hv = (1.0f - z) * n + z * hv;
                    op[(size_t)t * KF + lane] = hv;
                }
            }
        }
    }
}

extern "C" void kernel_launch(void* const* d_in, const int* in_sizes, int n_in,
                              void* d_out, int out_size)
{
    const float* x    = (const float*)d_in[0];
    const float* eWih = (const float*)d_in[1];
    const float* eWhh = (const float*)d_in[2];
    const float* ebih = (const float*)d_in[3];
    const float* ebhh = (const float*)d_in[4];
    const float* fcW  = (const float*)d_in[5];
    const float* fcb  = (const float*)d_in[6];
    const float* dWih = (const float*)d_in[7];
    const float* dWhh = (const float*)d_in[8];
    const float* dbih = (const float*)d_in[9];
    const float* dbhh = (const float*)d_in[10];
    float* out = (float*)d_out;

    const int writeEmb = (out_size >= KB * KT * KF + KB * KH) ? 1 : 0;

    enc_kernel<<<(KB / KBPC) * KCL, KTHR>>>(
        x, eWih, eWhh, ebih, ebhh, fcW, fcb, dWih, dWhh, dbih, dbhh,
        out, writeEmb);
}

// round 15
// speedup vs baseline: 1.1368x; 1.0336x over previous
#include <cuda_runtime.h>
#include <cstdint>

// ---------------------------------------------------------------------------
// Fully fused GRU acoustic model (single kernel):
//   encoder GRU(13->300) T=2048, fc+relu, decoder GRU(300->13) T=2048.
//
// 16 clusters x 8 CTAs x 512 thr. Cluster = 4 batches. Encoder: each thread
// owns TWO gate-rows x one 38-k chunk of Whh packed f32x2 in registers; h
// loaded via LDS.64 broadcast (R8 stage-1, proven fastest). Per step:
//   stage1 -> syncthreads -> tail (warps 0-4: reduce+gates+DSMEM push)
//   -> barrier.cluster.ARRIVE -> [gi(t+1) on warps 5-9 || x(t+2) prefetch
//   on warps 10-11, in the barrier shadow] -> barrier.cluster.WAIT.
// ---------------------------------------------------------------------------

#define KB   64
#define KT   2048
#define KF   13
#define KH   300
#define KCL  8      // CTAs per cluster
#define KBPC 4      // batches per cluster
#define KU   38     // hidden units per CTA (rank 7 uses 34)
#define KROWS 114   // 3 * KU gate rows per CTA
#define KTHR 512
#define KHP  304    // padded k extent per batch row (8 chunks * 38)
#define NCH  8      // k-chunks
#define CK   38     // k per chunk
#define CPAIR 19    // k-pairs per chunk
#define PSTR 36     // part row stride in floats

typedef unsigned long long u64t;

struct EncSmem {
    float h[2][KBPC][KHP];       // double-buffered hidden, [buf][batch][k]
    float part[KROWS][PSTR];     // partials [row][chunk*4+batch]; reused as
                                 // emb/dgi scratch post-encoder
    float WihT[16][128];         // input weights transposed [f][row]
    float gis[2][120][KBPC];     // double-buffered gate-input terms:
                                 //   r,z rows: gi + bih + bhh
                                 //   n rows:   gi + bih
    float bsumF[128];            // r,z rows: bih+bhh ; n rows: bih
    float bhhN[64];              // bhh for n rows (jl)
    float xs[2][KBPC][16];       // x_t ring (parity by step)
};

__device__ __forceinline__ float sigm_fast(float v) {
    return __fdividef(1.0f, 1.0f + __expf(-v));
}
__device__ __forceinline__ float tanh_fast(float v) {
    return __fdividef(2.0f, 1.0f + __expf(-2.0f * v)) - 1.0f;
}
__device__ __forceinline__ void cluster_sync() {
    asm volatile("barrier.cluster.arrive.aligned;\n\t"
                 "barrier.cluster.wait.aligned;" ::: "memory");
}
__device__ __forceinline__ uint32_t smem_u32(const void* p) {
    uint32_t a;
    asm("{ .reg .u64 t; cvta.to.shared.u64 t, %1; cvt.u32.u64 %0, t; }"
        : "=r"(a) : "l"(p));
    return a;
}
__device__ __forceinline__ uint32_t mapa_u32(uint32_t laddr, uint32_t rank) {
    uint32_t ra;
    asm("mapa.shared::cluster.u32 %0, %1, %2;" : "=r"(ra) : "r"(laddr), "r"(rank));
    return ra;
}
__device__ __forceinline__ void st_cluster_f32(uint32_t addr, float v) {
    asm volatile("st.shared::cluster.f32 [%0], %1;" :: "r"(addr), "f"(v) : "memory");
}
__device__ __forceinline__ u64t lds_b64(uint32_t addr) {
    u64t v;
    asm volatile("ld.shared.b64 %0, [%1];" : "=l"(v) : "r"(addr));
    return v;
}
__device__ __forceinline__ u64t pack2(float lo, float hi) {
    u64t v;
    asm("mov.b64 %0, {%1, %2};" : "=l"(v) : "f"(lo), "f"(hi));
    return v;
}
__device__ __forceinline__ float hadd2(u64t v) {
    float lo, hi;
    asm("mov.b64 {%0, %1}, %2;" : "=f"(lo), "=f"(hi) : "l"(v));
    return lo + hi;
}
__device__ __forceinline__ void fma2(u64t& d, u64t a, u64t b) {
    asm("fma.rn.f32x2 %0, %1, %2, %0;" : "+l"(d) : "l"(a), "l"(b));
}

__global__ void __cluster_dims__(KCL, 1, 1) __launch_bounds__(KTHR, 1)
enc_kernel(const float* __restrict__ x,    const float* __restrict__ Wih,
           const float* __restrict__ Whh,  const float* __restrict__ bih,
           const float* __restrict__ bhh,
           const float* __restrict__ fcW,  const float* __restrict__ fcb,
           const float* __restrict__ dWih, const float* __restrict__ dWhh,
           const float* __restrict__ dbih, const float* __restrict__ dbhh,
           float* __restrict__ out, int writeEmb)
{
    __shared__ __align__(16) EncSmem S;
    const int tid     = threadIdx.x;
    const int cluster = blockIdx.x / KCL;
    const int rank    = blockIdx.x % KCL;
    const int u0      = rank * KU;
    const int ucnt    = (KH - u0 < KU) ? (KH - u0) : KU;

    const int rp = tid & 63;       // row-pair index, active < 57
    const int c  = tid >> 6;       // k-chunk 0..7 (uniform per warp)
    const int r0 = 2 * rp;         // gate rows r0, r0+1
    const int k0 = c * CK;

    // ---- init smem ----
    for (int i = tid; i < 2 * KBPC * KHP; i += KTHR) (&S.h[0][0][0])[i] = 0.f;
    for (int i = tid; i < 16 * 128; i += KTHR) (&S.WihT[0][0])[i] = 0.f;
    for (int i = tid; i < 128; i += KTHR) S.bsumF[i] = 0.f;
    for (int i = tid; i < 64; i += KTHR) S.bhhN[i] = 0.f;
    __syncthreads();

    for (int i = tid; i < 3 * ucnt * KF; i += KTHR) {
        const int f  = i % KF;
        const int rr = i / KF;
        const int g = rr / ucnt, jl = rr % ucnt;
        S.WihT[f][g * KU + jl] = Wih[(size_t)(g * KH + u0 + jl) * KF + f];
    }
    if (tid < KROWS) {
        const int g = tid / KU, jl = tid % KU;
        if (jl < ucnt) {
            const float bi = bih[g * KH + u0 + jl];
            const float bh = bhh[g * KH + u0 + jl];
            if (g < 2) S.bsumF[tid] = bi + bh;   // r,z: fold both biases
            else       { S.bsumF[tid] = bi; S.bhhN[jl] = bh; }  // n: split
        }
    }
    // xs[0] = x_0 (for gis[0] precompute), xs[1] = x_1 (step-0 shadow gi)
    if (tid < KBPC * KF) {
        const int m = tid / KF, f = tid % KF;
        S.xs[0][m][f] = x[((size_t)(cluster * KBPC + m) * KT + 0) * KF + f];
    } else if (tid >= 160 && tid < 160 + KBPC * KF) {
        const int idx = tid - 160;
        const int m = idx / KF, f = idx % KF;
        S.xs[1][m][f] = x[((size_t)(cluster * KBPC + m) * KT + 1) * KF + f];
    }

    // ---- load this thread's TWO gate-rows of packed Whh k-pairs ----
    u64t Wa[CPAIR], Wb[CPAIR];
    {
        const int ga = r0 / KU,       jla = r0 % KU;
        const int gb = (r0 + 1) / KU, jlb = (r0 + 1) % KU;
        const bool actA = (rp < 57) && (r0 < KROWS)     && (jla < ucnt);
        const bool actB = (rp < 57) && (r0 + 1 < KROWS) && (jlb < ucnt);
        const float* wrA = actA ? (Whh + (size_t)(ga * KH + u0 + jla) * KH) : Whh;
        const float* wrB = actB ? (Whh + (size_t)(gb * KH + u0 + jlb) * KH) : Whh;
        #pragma unroll
        for (int i = 0; i < CPAIR; ++i) {
            const int k = k0 + 2 * i;
            float a0 = 0.f, a1 = 0.f, b0 = 0.f, b1 = 0.f;
            if (actA && k < KH)     a0 = wrA[k];
            if (actA && k + 1 < KH) a1 = wrA[k + 1];
            if (actB && k < KH)     b0 = wrB[k];
            if (actB && k + 1 < KH) b1 = wrB[k + 1];
            Wa[i] = pack2(a0, a1);
            Wb[i] = pack2(b0, b1);
        }
    }
    __syncthreads();

    // ---- precompute gis[0] from xs[0] ----
    if (tid < KBPC * KU) {
        const int jl = tid >> 2, m = tid & 3;
        if (jl < ucnt) {
            const float* xr = S.xs[0][m];
            float gr = S.bsumF[jl], gz = S.bsumF[KU + jl], gn = S.bsumF[2 * KU + jl];
            #pragma unroll
            for (int f = 0; f < KF; ++f) {
                const float xf = xr[f];
                gr = fmaf(S.WihT[f][jl], xf, gr);
                gz = fmaf(S.WihT[f][KU + jl], xf, gz);
                gn = fmaf(S.WihT[f][2 * KU + jl], xf, gn);
            }
            S.gis[0][jl][m] = gr;
            S.gis[0][KU + jl][m] = gz;
            S.gis[0][2 * KU + jl][m] = gn;
        }
    }

    // ---- hoisted DSMEM peer base addresses + step offsets ----
    const uint32_t hbaseL = smem_u32(&S.h[0][0][0]);
    uint32_t R0 = mapa_u32(hbaseL, 0), R1 = mapa_u32(hbaseL, 1),
             R2 = mapa_u32(hbaseL, 2), R3 = mapa_u32(hbaseL, 3),
             R4 = mapa_u32(hbaseL, 4), R5 = mapa_u32(hbaseL, 5),
             R6 = mapa_u32(hbaseL, 6), R7 = mapa_u32(hbaseL, 7);
    const int jl_t = tid >> 2, m_t = tid & 3;                    // tail mapping
    const uint32_t offA = ((KBPC + m_t) * KHP + u0 + jl_t) * 4;  // write h[1]
    const uint32_t offB = ((m_t) * KHP + u0 + jl_t) * 4;         // write h[0]

    __syncthreads();
    cluster_sync();   // peers' h buffers initialized before any remote store

    int p = 0;

    for (int t = 0; t < KT; ++t) {
        // ---- stage 1: two rows x one 38-k chunk; LDS.64 broadcast ----
        if (rp < 57) {
            const uint32_t hb = hbaseL + (uint32_t)(p * KBPC * KHP + k0) * 4;
            u64t A0 = 0, A1 = 0, A2 = 0, A3 = 0;   // row r0, batches 0..3
            u64t B0 = 0, B1 = 0, B2 = 0, B3 = 0;   // row r0+1
            #pragma unroll
            for (int i = 0; i < CPAIR; ++i) {
                const u64t h0 = lds_b64(hb + i * 8);
                const u64t h1 = lds_b64(hb + KHP * 4 + i * 8);
                const u64t h2 = lds_b64(hb + 2 * KHP * 4 + i * 8);
                const u64t h3 = lds_b64(hb + 3 * KHP * 4 + i * 8);
                const u64t wa = Wa[i], wb = Wb[i];
                fma2(A0, wa, h0); fma2(A1, wa, h1);
                fma2(A2, wa, h2); fma2(A3, wa, h3);
                fma2(B0, wb, h0); fma2(B1, wb, h1);
                fma2(B2, wb, h2); fma2(B3, wb, h3);
            }
            *reinterpret_cast<float4*>(&S.part[r0][c * 4]) =
                make_float4(hadd2(A0), hadd2(A1), hadd2(A2), hadd2(A3));
            *reinterpret_cast<float4*>(&S.part[r0 + 1][c * 4]) =
                make_float4(hadd2(B0), hadd2(B1), hadd2(B2), hadd2(B3));
        }
        __syncthreads();

        // ---- tail (warps 0-4): reduce, gates, DSMEM broadcast ----
        if (tid < KBPC * KU && jl_t < ucnt) {
            const int jl = jl_t, m = m_t;
            const float* pR = S.part[jl];
            const float* pZ = S.part[KU + jl];
            const float* pN = S.part[2 * KU + jl];
            float pr = 0.f, pz = 0.f, pn = 0.f;
            #pragma unroll
            for (int cc = 0; cc < NCH; ++cc) {
                pr += pR[cc * 4 + m];
                pz += pZ[cc * 4 + m];
                pn += pN[cc * 4 + m];
            }
            const float* gi = &S.gis[t & 1][0][0];
            const float r = sigm_fast(pr + gi[jl * 4 + m]);
            const float z = sigm_fast(pz + gi[(KU + jl) * 4 + m]);
            const float n = tanh_fast(gi[(2 * KU + jl) * 4 + m]
                                      + r * (pn + S.bhhN[jl]));
            const float hn = (1.0f - z) * n + z * S.h[p][m][u0 + jl];
            const uint32_t off = p ? offB : offA;
            st_cluster_f32(R0 + off, hn); st_cluster_f32(R1 + off, hn);
            st_cluster_f32(R2 + off, hn); st_cluster_f32(R3 + off, hn);
            st_cluster_f32(R4 + off, hn); st_cluster_f32(R5 + off, hn);
            st_cluster_f32(R6 + off, hn); st_cluster_f32(R7 + off, hn);
        }

        // ---- release this CTA's contribution; overlap shadow work ----
        asm volatile("barrier.cluster.arrive.aligned;" ::: "memory");

        if (tid >= 160 && tid < 160 + KBPC * KU) {
            // gi for step t+1 (h-independent) in the barrier shadow.
            // Read by the tail at t+1 only after stage-1's __syncthreads.
            if (t + 1 < KT) {
                const int idx = tid - 160;
                const int jl = idx >> 2, m = idx & 3;
                if (jl < ucnt) {
                    const float* xr = S.xs[(t + 1) & 1][m];
                    float gr = S.bsumF[jl], gz = S.bsumF[KU + jl],
                          gn = S.bsumF[2 * KU + jl];
                    #pragma unroll
                    for (int f = 0; f < KF; ++f) {
                        const float xf = xr[f];
                        gr = fmaf(S.WihT[f][jl], xf, gr);
                        gz = fmaf(S.WihT[f][KU + jl], xf, gz);
                        gn = fmaf(S.WihT[f][2 * KU + jl], xf, gn);
                    }
                    S.gis[(t + 1) & 1][jl][m] = gr;
                    S.gis[(t + 1) & 1][KU + jl][m] = gz;
                    S.gis[(t + 1) & 1][2 * KU + jl][m] = gn;
                }
            }
        } else if (tid >= 312 && tid < 312 + KBPC * KF) {
            // prefetch x_{t+2} into the xs slot freed this step
            if (t + 2 < KT) {
                const int idx = tid - 312;
                const int pm = idx / KF, pf = idx % KF;
                S.xs[(t + 2) & 1][pm][pf] =
                    x[((size_t)(cluster * KBPC + pm) * KT + (t + 2)) * KF + pf];
            }
        }

        asm volatile("barrier.cluster.wait.aligned;" ::: "memory");
        p ^= 1;
    }
    __syncthreads();

    // =======================================================================
    // Fused fc + relu + decoder: ranks 0-3 handle batch m = rank.
    // =======================================================================
    if (rank < KBPC) {
        const int m = rank;
        const int b = cluster * KBPC + m;
        float* embS = &S.part[0][0];       // 300 floats (reuse part scratch)
        float* dgiS = embS + 304;          // 39 floats

        const float* hrow = &S.h[p][m][0];
        for (int j = tid; j < KH; j += KTHR) {
            const float4* wr = reinterpret_cast<const float4*>(fcW + (size_t)j * KH);
            float s0 = 0.f, s1 = 0.f, s2 = 0.f, s3 = 0.f;
            #pragma unroll 5
            for (int k = 0; k < KH / 4; ++k) {
                const float4 w4 = wr[k];
                const float4 h4 = *reinterpret_cast<const float4*>(&hrow[k * 4]);
                s0 = fmaf(w4.x, h4.x, s0); s1 = fmaf(w4.y, h4.y, s1);
                s2 = fmaf(w4.z, h4.z, s2); s3 = fmaf(w4.w, h4.w, s3);
            }
            float s = fcb[j] + ((s0 + s1) + (s2 + s3));
            s = fmaxf(s, 0.0f);
            embS[j] = s;
            if (writeEmb)
                out[(size_t)KB * KT * KF + (size_t)b * KH + j] = s;
        }
        __syncthreads();

        if (tid < 3 * KF) {
            const float4* wr = reinterpret_cast<const float4*>(dWih + (size_t)tid * KH);
            float s0 = 0.f, s1 = 0.f, s2 = 0.f, s3 = 0.f;
            #pragma unroll 5
            for (int k = 0; k < KH / 4; ++k) {
                const float4 w4 = wr[k];
                const float4 h4 = *reinterpret_cast<const float4*>(&embS[k * 4]);
                s0 = fmaf(w4.x, h4.x, s0); s1 = fmaf(w4.y, h4.y, s1);
                s2 = fmaf(w4.z, h4.z, s2); s3 = fmaf(w4.w, h4.w, s3);
            }
            dgiS[tid] = dbih[tid] + ((s0 + s1) + (s2 + s3));
        }
        __syncthreads();

        if (tid < 32) {
            const int lane = tid;
            const bool act = (lane < KF);
            float wr_[KF], wz_[KF], wn_[KF];
            #pragma unroll
            for (int k = 0; k < KF; ++k) {
                wr_[k] = act ? dWhh[(size_t)lane * KF + k]            : 0.f;
                wz_[k] = act ? dWhh[(size_t)(KF + lane) * KF + k]     : 0.f;
                wn_[k] = act ? dWhh[(size_t)(2 * KF + lane) * KF + k] : 0.f;
            }
            const float bhr = act ? dbhh[lane]          : 0.f;
            const float bhz = act ? dbhh[KF + lane]     : 0.f;
            const float bhn = act ? dbhh[2 * KF + lane] : 0.f;
            const float dgr = act ? dgiS[lane]          : 0.f;
            const float dgz = act ? dgiS[KF + lane]     : 0.f;
            const float dgn = act ? dgiS[2 * KF + lane] : 0.f;
            float hv = 0.f;
            float* op = out + (size_t)b * KT * KF;

            for (int t = 0; t < KT; ++t) {
                float sr = bhr, sz = bhz, sn = bhn;
                #pragma unroll
                for (int k = 0; k < KF; ++k) {
                    const float hk = __shfl_sync(0xffffffffu, hv, k);
                    sr = fmaf(wr_[k], hk, sr);
                    sz = fmaf(wz_[k], hk, sz);
                    sn = fmaf(wn_[k], hk, sn);
                }
                if (act) {
                    const float r = sigm_fast(dgr + sr);
                    const float z = sigm_fast(dgz + sz);
                    const float n = tanh_fast(dgn + r * sn);
                    hv = (1.0f - z) * n + z * hv;
                    op[(size_t)t * KF + lane] = hv;
                }
            }
        }
    }
}

extern "C" void kernel_launch(void* const* d_in, const int* in_sizes, int n_in,
                              void* d_out, int out_size)
{
    const float* x    = (const float*)d_in[0];
    const float* eWih = (const float*)d_in[1];
    const float* eWhh = (const float*)d_in[2];
    const float* ebih = (const float*)d_in[3];
    const float* ebhh = (const float*)d_in[4];
    const float* fcW  = (const float*)d_in[5];
    const float* fcb  = (const float*)d_in[6];
    const float* dWih = (const float*)d_in[7];
    const float* dWhh = (const float*)d_in[8];
    const float* dbih = (const float*)d_in[9];
    const float* dbhh = (const float*)d_in[10];
    float* out = (float*)d_out;

    const int writeEmb = (out_size >= KB * KT * KF + KB * KH) ? 1 : 0;

    enc_kernel<<<(KB / KBPC) * KCL, KTHR>>>(
        x, eWih, eWhh, ebih, ebhh, fcW, fcb, dWih, dWhh, dbih, dbhh,
        out, writeEmb);
}